// round 1
// baseline (speedup 1.0000x reference)
#include <cuda_runtime.h>
#include <cuda_bf16.h>
#include <math.h>

// Problem constants
#define B_  64
#define S_  2048
#define H_  512
#define M_  (B_ * S_)   // 131072 GEMM rows

// Scratch (device globals — no allocations allowed)
__device__ float g_comb[B_ * H_];   // dec_f + bh + bc + bs  per (b, n)
__device__ float g_e[B_ * S_];      // e_t logits

// ---------------------------------------------------------------------------
// Kernel 1: comb[b][n] = sum_h dec[b][h]*Ws[h][n] + bs[n] + bh[n] + bc[n]
// ---------------------------------------------------------------------------
__global__ void dec_comb_kernel(const float* __restrict__ dec,
                                const float* __restrict__ Ws,
                                const float* __restrict__ bs,
                                const float* __restrict__ bh,
                                const float* __restrict__ bc)
{
    int b = blockIdx.x;
    __shared__ float dh[H_];
    for (int i = threadIdx.x; i < H_; i += blockDim.x)
        dh[i] = dec[b * H_ + i];
    __syncthreads();

    for (int n = threadIdx.x; n < H_; n += blockDim.x) {
        float acc = 0.f;
        #pragma unroll 8
        for (int h = 0; h < H_; ++h)
            acc = fmaf(dh[h], Ws[h * H_ + n], acc);
        g_comb[b * H_ + n] = acc + bs[n] + bh[n] + bc[n];
    }
}

// ---------------------------------------------------------------------------
// Kernel 2: fused GEMM (enc @ Wh) -> tanh(+biases+cov*Wc) -> dot(v_w) -> e_t
// Tile: BM=128 rows, BN=128 cols (x4 chunks for N=512), BK=8, 256 threads, 8x8/thread
// ---------------------------------------------------------------------------
#define BM 128
#define BN 128
#define BK 8

__global__ __launch_bounds__(256, 2)
void attn_gemm_kernel(const float* __restrict__ A,    // [M_, H_] encoder_output
                      const float* __restrict__ Wh,   // [H_, H_]
                      const float* __restrict__ Wc,   // [H_]
                      const float* __restrict__ cov,  // [M_]
                      const float* __restrict__ v_w)  // [H_]
{
    __shared__ float As[BK][BM];
    __shared__ float Bs[BK][BN];
    __shared__ float ered[BM][17];   // padded reduction buffer

    const int tid   = threadIdx.x;
    const int tx    = tid & 15;      // 0..15  -> col group
    const int ty    = tid >> 4;      // 0..15  -> row group
    const int mBase = blockIdx.x * BM;
    const int b     = mBase >> 11;   // / 2048 (BM divides S)

    // A-tile load mapping: 128 rows x 8 cols = 256 float4
    const int arow  = tid >> 1;          // 0..127
    const int acol4 = (tid & 1) << 2;    // 0 or 4
    // B-tile load mapping: 8 rows x 128 cols = 256 float4
    const int brow  = tid >> 5;          // 0..7
    const int bcol4 = (tid & 31) << 2;   // 0..124

    // Per-thread row-local data
    float cov_row[8];
    #pragma unroll
    for (int i = 0; i < 8; ++i)
        cov_row[i] = cov[mBase + ty * 8 + i];

    float e_part[8];
    #pragma unroll
    for (int i = 0; i < 8; ++i) e_part[i] = 0.f;

    const float* combB = &g_comb[b * H_];

    for (int nc = 0; nc < H_ / BN; ++nc) {
        const int nBase = nc * BN;

        float acc[8][8];
        #pragma unroll
        for (int i = 0; i < 8; ++i)
            #pragma unroll
            for (int j = 0; j < 8; ++j) acc[i][j] = 0.f;

        for (int k0 = 0; k0 < H_; k0 += BK) {
            // load A tile (transposed into As[k][m])
            {
                const float4 va = *reinterpret_cast<const float4*>(
                    &A[(size_t)(mBase + arow) * H_ + k0 + acol4]);
                As[acol4 + 0][arow] = va.x;
                As[acol4 + 1][arow] = va.y;
                As[acol4 + 2][arow] = va.z;
                As[acol4 + 3][arow] = va.w;
            }
            // load B tile
            {
                const float4 vb = *reinterpret_cast<const float4*>(
                    &Wh[(size_t)(k0 + brow) * H_ + nBase + bcol4]);
                *reinterpret_cast<float4*>(&Bs[brow][bcol4]) = vb;
            }
            __syncthreads();

            #pragma unroll
            for (int kk = 0; kk < BK; ++kk) {
                float af[8], bf[8];
                #pragma unroll
                for (int i = 0; i < 8; ++i) af[i] = As[kk][ty * 8 + i];
                #pragma unroll
                for (int j = 0; j < 8; ++j) bf[j] = Bs[kk][tx * 8 + j];
                #pragma unroll
                for (int i = 0; i < 8; ++i)
                    #pragma unroll
                    for (int j = 0; j < 8; ++j)
                        acc[i][j] = fmaf(af[i], bf[j], acc[i][j]);
            }
            __syncthreads();
        }

        // Fused epilogue: tanh + v-dot partial accumulation
        #pragma unroll
        for (int j = 0; j < 8; ++j) {
            const int n  = nBase + tx * 8 + j;
            const float cb = combB[n];
            const float wc = Wc[n];
            const float vw = v_w[n];
            #pragma unroll
            for (int i = 0; i < 8; ++i) {
                float t = tanhf(acc[i][j] + cb + cov_row[i] * wc);
                e_part[i] = fmaf(vw, t, e_part[i]);
            }
        }
        __syncthreads();  // before tiles are reloaded next chunk
    }

    // Reduce e_part across the 16 tx-threads sharing each row
    #pragma unroll
    for (int i = 0; i < 8; ++i)
        ered[ty * 8 + i][tx] = e_part[i];
    __syncthreads();

    if (tid < BM) {
        float s = 0.f;
        #pragma unroll
        for (int t = 0; t < 16; ++t) s += ered[tid][t];
        g_e[mBase + tid] = s;
    }
}

// ---------------------------------------------------------------------------
// Kernel 3: per-batch softmax over S=2048 + coverage update.
// (v_b is a constant shift -> softmax-invariant -> dropped.)
// out[0 : B*S]      = a_t
// out[B*S : 2*B*S]  = coverage + a_t
// ---------------------------------------------------------------------------
__global__ __launch_bounds__(256)
void softmax_kernel(const float* __restrict__ cov, float* __restrict__ out)
{
    const int b   = blockIdx.x;
    const int tid = threadIdx.x;
    __shared__ float red[256];

    float local[8];
    float mx = -INFINITY;
    #pragma unroll
    for (int i = 0; i < 8; ++i) {
        local[i] = g_e[b * S_ + tid + i * 256];
        mx = fmaxf(mx, local[i]);
    }

    red[tid] = mx;
    __syncthreads();
    for (int s = 128; s > 0; s >>= 1) {
        if (tid < s) red[tid] = fmaxf(red[tid], red[tid + s]);
        __syncthreads();
    }
    const float m = red[0];
    __syncthreads();

    float sum = 0.f;
    #pragma unroll
    for (int i = 0; i < 8; ++i) {
        local[i] = expf(local[i] - m);
        sum += local[i];
    }
    red[tid] = sum;
    __syncthreads();
    for (int s = 128; s > 0; s >>= 1) {
        if (tid < s) red[tid] += red[tid + s];
        __syncthreads();
    }
    const float inv = 1.0f / red[0];

    #pragma unroll
    for (int i = 0; i < 8; ++i) {
        const int idx = b * S_ + tid + i * 256;
        const float a = local[i] * inv;
        out[idx]           = a;
        out[B_ * S_ + idx] = cov[idx] + a;
    }
}

// ---------------------------------------------------------------------------
// Launch
// ---------------------------------------------------------------------------
extern "C" void kernel_launch(void* const* d_in, const int* in_sizes, int n_in,
                              void* d_out, int out_size)
{
    const float* enc  = (const float*)d_in[0];   // [B,S,H]
    const float* dec  = (const float*)d_in[1];   // [B,H]
    const float* cov  = (const float*)d_in[2];   // [B,S]
    const float* Wh   = (const float*)d_in[3];   // [H,H]
    const float* bh   = (const float*)d_in[4];   // [H]
    const float* Ws   = (const float*)d_in[5];   // [H,H]
    const float* bs   = (const float*)d_in[6];   // [H]
    const float* Wc   = (const float*)d_in[7];   // [1,H] -> H floats
    const float* bc   = (const float*)d_in[8];   // [H]
    const float* v_w  = (const float*)d_in[9];   // [H]
    // d_in[10] = v_b : softmax-invariant, unused
    float* out = (float*)d_out;

    dec_comb_kernel<<<B_, 256>>>(dec, Ws, bs, bh, bc);
    attn_gemm_kernel<<<M_ / BM, 256>>>(enc, Wh, Wc, cov, v_w);
    softmax_kernel<<<B_, 256>>>(cov, out);
}